// round 15
// baseline (speedup 1.0000x reference)
#include <cuda_runtime.h>
#include <cuda_fp16.h>
#include <math.h>
#include <stdint.h>

// ---------------- problem constants ----------------
#define T_DIM 100
#define B_DIM 128
#define C0 700
#define C0P 704
#define C1 256
#define C3 20
#define N3P 32
#define L_TAPS 25
#define PADR (24 * B_DIM)
#define M_DIM (T_DIM * B_DIM)        // 12800
#define ROWS_PAD (PADR + M_DIM)      // 15872

// ---------------- device scratch ----------------
__device__ __align__(16) __half g_xh[ROWS_PAD * C0P];
__device__ __align__(16) __half g_ah[ROWS_PAD * C1];
__device__ __align__(16) float g_conv[3 * M_DIM * C1];
__device__ __align__(16) float g_sum[M_DIM * C1];
__device__ __align__(16) float g_logits[4 * M_DIM * C3];
__device__ __align__(16) __half g_K1h[L_TAPS * C1 * C0P];
__device__ __align__(16) __half g_K2h[L_TAPS * C1 * C1];
__device__ __align__(16) __half g_K3h[L_TAPS * N3P * C1];
__device__ __align__(16) float g_part[128 * 2 * 256];
__device__ float g_scale[256];
__device__ float g_shift[256];
__device__ unsigned long long g_ticket = 0;
__device__ volatile unsigned long long g_flag = 0;

// ---------------- PTX helpers (sm_80-compatible ISA only) ----------------
__device__ __forceinline__ uint32_t smem_u32(const void* p) {
    uint32_t a;
    asm("{ .reg .u64 t; cvta.to.shared.u64 t, %1; cvt.u32.u64 %0, t; }" : "=r"(a) : "l"(p));
    return a;
}
__device__ __forceinline__ void ldsm_x4(uint32_t& r0, uint32_t& r1, uint32_t& r2, uint32_t& r3,
                                        uint32_t addr) {
    asm volatile("ldmatrix.sync.aligned.m8n8.x4.shared.b16 {%0,%1,%2,%3}, [%4];"
                 : "=r"(r0), "=r"(r1), "=r"(r2), "=r"(r3) : "r"(addr));
}
__device__ __forceinline__ void mma16816(float* c, const uint32_t* a, const uint32_t* b) {
    asm volatile(
        "mma.sync.aligned.m16n8k16.row.col.f32.f16.f16.f32 "
        "{%0,%1,%2,%3}, {%4,%5,%6,%7}, {%8,%9}, {%0,%1,%2,%3};"
        : "+f"(c[0]), "+f"(c[1]), "+f"(c[2]), "+f"(c[3])
        : "r"(a[0]), "r"(a[1]), "r"(a[2]), "r"(a[3]), "r"(b[0]), "r"(b[1]));
}
// fp16-accumulate variant: C/D are 2 regs of half2 (same positions, packed)
__device__ __forceinline__ void mma16816_h(uint32_t* c, const uint32_t* a, const uint32_t* b) {
    asm volatile(
        "mma.sync.aligned.m16n8k16.row.col.f16.f16.f16.f16 "
        "{%0,%1}, {%2,%3,%4,%5}, {%6,%7}, {%0,%1};"
        : "+r"(c[0]), "+r"(c[1])
        : "r"(a[0]), "r"(a[1]), "r"(a[2]), "r"(a[3]), "r"(b[0]), "r"(b[1]));
}
__device__ __forceinline__ void cp16(uint32_t s, const void* g) {
    asm volatile("cp.async.cg.shared.global [%0], [%1], 16;" :: "r"(s), "l"(g));
}
#define CP_COMMIT()  asm volatile("cp.async.commit_group;" ::: "memory")
#define CP_WAIT(n)   asm volatile("cp.async.wait_group %0;" :: "n"(n) : "memory")

// ---------------- fused setup kernel ----------------
__device__ __forceinline__ void build_elem(const float* __restrict__ W,
                                           const float* __restrict__ P,
                                           __half* __restrict__ Kh,
                                           int Cin, int Cinp, int Cout, int Npad, int idx) {
    int i = idx % Cinp;
    int n = idx / Cinp;
    if (n < Cout && i < Cin) {
        float p = P[n * Cin + i];
        float w = W[n * Cin + i];
        float k[L_TAPS], z = 0.f;
#pragma unroll
        for (int l = 0; l < L_TAPS; ++l) {
            float d = ((float)(l - 12) - p) * (1.f / 12.f);
            k[l] = expf(-0.5f * d * d);
            z += k[l];
        }
        float sc = w / (z + 1e-7f);
#pragma unroll
        for (int l = 0; l < L_TAPS; ++l)
            Kh[((size_t)l * Npad + n) * Cinp + i] = __float2half(k[l] * sc);
    } else {
#pragma unroll
        for (int l = 0; l < L_TAPS; ++l)
            Kh[((size_t)l * Npad + n) * Cinp + i] = __float2half(0.f);
    }
}

#define G_INPUT ((ROWS_PAD * C0P / 2 + 255) / 256)
#define N_BUILD (256 * C0P + 256 * C1 + N3P * C1)
#define G_BUILD ((N_BUILD + 255) / 256)

__global__ void setup_all(const float* __restrict__ x,
                          const float* __restrict__ W1, const float* __restrict__ P1,
                          const float* __restrict__ W2, const float* __restrict__ P2,
                          const float* __restrict__ W3, const float* __restrict__ P3) {
    if (blockIdx.x < G_INPUT) {
        int i = blockIdx.x * blockDim.x + threadIdx.x;
        if (i >= ROWS_PAD * C0P / 2) return;
        int c2 = (i % (C0P / 2)) * 2;
        int row = i / (C0P / 2);
        float2 v = make_float2(0.f, 0.f);
        if (row >= PADR && c2 < C0) {
            int m = row - PADR;
            int t = m >> 7, b = m & 127;
            v = *(const float2*)&x[((size_t)b * T_DIM + t) * C0 + c2];
        }
        ((__half2*)g_xh)[i] = __floats2half2_rn(v.x, v.y);
        if (i < PADR * C1 / 2)
            ((__half2*)g_ah)[i] = __floats2half2_rn(0.f, 0.f);
    } else {
        int i = (blockIdx.x - G_INPUT) * blockDim.x + threadIdx.x;
        const int R1 = 256 * C0P, R2 = 256 * C1, R3 = N3P * C1;
        if (i < R1) build_elem(W1, P1, g_K1h, C0, C0P, 256, 256, i);
        else if (i < R1 + R2) build_elem(W2, P2, g_K2h, C1, C1, 256, 256, i - R1);
        else if (i < R1 + R2 + R3) build_elem(W3, P3, g_K3h, C1, C1, C3, N3P, i - R1 - R2);
    }
}

// ---------------- warp-tiled mma.sync conv-GEMM ----------------
// ACCF16=1: each K=16 dot runs in fp16-acc HMMA (2x rate), folded to fp32
// immediately (per-instruction) -> bounded rounding error.
template <int CIN, int BM, int BN, int WR, int WC, int NTOT, int NSPLIT, int KSPLIT,
          int MAXOCC, int ACCF16>
__global__ __launch_bounds__(256, MAXOCC)
void conv_mma(const __half* __restrict__ Ah, const __half* __restrict__ Bh,
              float* __restrict__ Y, int ldY, int ncol) {
    constexpr int KCH = CIN / 64;
    constexpr int NCHUNK = L_TAPS * KCH;
    constexpr int LEN = (NCHUNK + KSPLIT - 1) / KSPLIT;
    constexpr int WM = BM / WR, WN = BN / WC;
    constexpr int MT = WM / 16, NT = WN / 8;
    constexpr int ASTR = 144;
    constexpr int ASZ = BM * ASTR, BSZ = BN * ASTR;
    constexpr int STG = ASZ + BSZ;

    extern __shared__ char smem[];
    uint32_t s_base = smem_u32(smem);

    int tid = threadIdx.x, wid = tid >> 5, lane = tid & 31;
    int m0 = blockIdx.x * BM;
    int npart = blockIdx.y % NSPLIT;
    int kpart = blockIdx.y / NSPLIT;
    int n0 = npart * BN;
    int q0 = kpart * LEN;
    int q1 = (q0 + LEN < NCHUNK) ? q0 + LEN : NCHUNK;
    float* Yb = Y + (size_t)kpart * M_DIM * ldY;

    int warp_m = (wid % WR) * WM;
    int warp_n = (wid / WR) * WN;

    float acc[MT][NT][4];
#pragma unroll
    for (int i = 0; i < MT; ++i)
#pragma unroll
        for (int j = 0; j < NT; ++j)
#pragma unroll
            for (int q = 0; q < 4; ++q) acc[i][j][q] = 0.f;

    auto issue = [&](int q) {
        int s = q % 3;
        int l = q / KCH;
        int k0 = (q - l * KCH) * 64;
        const __half* Abase = Ah + (size_t)(m0 + l * B_DIM) * CIN + k0;
        const __half* Bbase = Bh + (size_t)(l * NTOT + n0) * CIN + k0;
        uint32_t as = s_base + s * STG;
        uint32_t bs = as + ASZ;
#pragma unroll
        for (int j = 0; j < BM * 8 / 256; ++j) {
            int tf = tid + j * 256;
            int r = tf >> 3, cc = (tf & 7) * 8;
            cp16(as + r * ASTR + cc * 2, Abase + (size_t)r * CIN + cc);
        }
#pragma unroll
        for (int j = 0; j < BN * 8 / 256; ++j) {
            int tf = tid + j * 256;
            int r = tf >> 3, cc = (tf & 7) * 8;
            cp16(bs + r * ASTR + cc * 2, Bbase + (size_t)r * CIN + cc);
        }
        CP_COMMIT();
    };

    issue(q0);
    if (q0 + 1 < q1) issue(q0 + 1);
    for (int q = q0; q < q1; ++q) {
        if (q == q1 - 1) { CP_WAIT(0); }
        else             { CP_WAIT(1); }
        __syncthreads();
        if (q + 2 < q1) issue(q + 2);
        int s = q % 3;
        uint32_t as = s_base + s * STG;
        uint32_t bs = as + ASZ;
#pragma unroll
        for (int kk = 0; kk < 4; ++kk) {
            uint32_t a[MT][4];
            uint32_t b[NT][2];
#pragma unroll
            for (int mt = 0; mt < MT; ++mt) {
                uint32_t addr = as + (warp_m + mt * 16 + (lane & 15)) * ASTR
                              + (kk * 16 + (lane >> 4) * 8) * 2;
                ldsm_x4(a[mt][0], a[mt][1], a[mt][2], a[mt][3], addr);
            }
#pragma unroll
            for (int nt = 0; nt < NT; nt += 2) {
                uint32_t addr = bs + (warp_n + (nt + (lane >> 4)) * 8 + (lane & 7)) * ASTR
                              + (kk * 16 + ((lane >> 3) & 1) * 8) * 2;
                ldsm_x4(b[nt][0], b[nt][1], b[nt + 1][0], b[nt + 1][1], addr);
            }
#pragma unroll
            for (int mt = 0; mt < MT; ++mt)
#pragma unroll
                for (int nt = 0; nt < NT; ++nt) {
                    if (ACCF16) {
                        uint32_t h[2] = {0u, 0u};
                        mma16816_h(h, a[mt], b[nt]);
                        float2 f0 = __half22float2(*(__half2*)&h[0]);
                        float2 f1 = __half22float2(*(__half2*)&h[1]);
                        acc[mt][nt][0] += f0.x; acc[mt][nt][1] += f0.y;
                        acc[mt][nt][2] += f1.x; acc[mt][nt][3] += f1.y;
                    } else {
                        mma16816(acc[mt][nt], a[mt], b[nt]);
                    }
                }
        }
    }

    int rq2 = lane >> 2, cq = (lane & 3) * 2;
#pragma unroll
    for (int mt = 0; mt < MT; ++mt)
#pragma unroll
        for (int nt = 0; nt < NT; ++nt) {
            int n = n0 + warp_n + nt * 8 + cq;
            if (n < ncol) {
                int m = m0 + warp_m + mt * 16 + rq2;
                *(float2*)&Yb[(size_t)m * ldY + n] =
                    make_float2(acc[mt][nt][0], acc[mt][nt][1]);
                *(float2*)&Yb[(size_t)(m + 8) * ldY + n] =
                    make_float2(acc[mt][nt][2], acc[mt][nt][3]);
            }
        }
}

// ---------------- fused BN (stats + finalize + ReLU->fp16) ----------------
__global__ __launch_bounds__(256, 1)
void bn_fused(const float* __restrict__ X,
              const float* __restrict__ gamma, const float* __restrict__ beta) {
    __shared__ float4 ss[4][64], qq[4][64];
    __shared__ unsigned long long sh_ticket;
    int bl = blockIdx.x;
    int cg = threadIdx.x & 63;
    int rg = threadIdx.x >> 6;
    int c4 = cg * 4;

    float4 s = make_float4(0.f, 0.f, 0.f, 0.f);
    float4 qv = make_float4(0.f, 0.f, 0.f, 0.f);
    for (int r = rg; r < 100; r += 4) {
        size_t idx = (size_t)(bl * 100 + r) * 64 + cg;
        float4 v0 = ((const float4*)X)[idx];
        float4 v1 = ((const float4*)X)[(size_t)M_DIM * 64 + idx];
        float4 v2 = ((const float4*)X)[(size_t)2 * M_DIM * 64 + idx];
        float4 v;
        v.x = v0.x + v1.x + v2.x; v.y = v0.y + v1.y + v2.y;
        v.z = v0.z + v1.z + v2.z; v.w = v0.w + v1.w + v2.w;
        ((float4*)g_sum)[idx] = v;
        s.x += v.x; s.y += v.y; s.z += v.z; s.w += v.w;
        qv.x += v.x * v.x; qv.y += v.y * v.y; qv.z += v.z * v.z; qv.w += v.w * v.w;
    }
    ss[rg][cg] = s; qq[rg][cg] = qv;
    __syncthreads();
    if (rg == 0) {
        float4 s1 = ss[1][cg], s2 = ss[2][cg], s3 = ss[3][cg];
        float4 q1 = qq[1][cg], q2 = qq[2][cg], q3 = qq[3][cg];
        s.x += s1.x + s2.x + s3.x; s.y += s1.y + s2.y + s3.y;
        s.z += s1.z + s2.z + s3.z; s.w += s1.w + s2.w + s3.w;
        qv.x += q1.x + q2.x + q3.x; qv.y += q1.y + q2.y + q3.y;
        qv.z += q1.z + q2.z + q3.z; qv.w += q1.w + q2.w + q3.w;
        *(float4*)&g_part[bl * 512 + c4] = s;
        *(float4*)&g_part[bl * 512 + 256 + c4] = qv;
    }
    __threadfence();
    __syncthreads();
    if (threadIdx.x == 0) sh_ticket = atomicAdd(&g_ticket, 1ULL);
    __syncthreads();
    unsigned long long ticket = sh_ticket;
    unsigned long long epoch = ticket / 128ULL;
    bool last = (ticket % 128ULL) == 127ULL;

    if (last) {
        __threadfence();
        int c = threadIdx.x;
        float st = 0.f, qt = 0.f;
#pragma unroll 8
        for (int b2 = 0; b2 < 128; ++b2) {
            st += g_part[b2 * 512 + c];
            qt += g_part[b2 * 512 + 256 + c];
        }
        float mean = st * (1.f / (float)M_DIM);
        float var = qt * (1.f / (float)M_DIM) - mean * mean;
        float sc = gamma[c] * rsqrtf(var + 1e-5f);
        g_scale[c] = sc;
        g_shift[c] = beta[c] - mean * sc;
        __threadfence();
        __syncthreads();
        if (threadIdx.x == 0) g_flag = epoch + 1ULL;
    } else {
        if (threadIdx.x == 0) {
            while (g_flag < epoch + 1ULL) { }
        }
        __syncthreads();
        __threadfence();
    }

    float sc0 = g_scale[c4 + 0], sc1 = g_scale[c4 + 1];
    float sc2 = g_scale[c4 + 2], sc3 = g_scale[c4 + 3];
    float sf0 = g_shift[c4 + 0], sf1 = g_shift[c4 + 1];
    float sf2 = g_shift[c4 + 2], sf3 = g_shift[c4 + 3];
    for (int r = rg; r < 100; r += 4) {
        size_t idx = (size_t)(bl * 100 + r) * 64 + cg;
        float4 v = ((const float4*)g_sum)[idx];
        float r0 = fmaxf(sc0 * v.x + sf0, 0.f);
        float r1 = fmaxf(sc1 * v.y + sf1, 0.f);
        float r2 = fmaxf(sc2 * v.z + sf2, 0.f);
        float r3 = fmaxf(sc3 * v.w + sf3, 0.f);
        ((__half2*)g_ah)[(size_t)PADR * 128 + idx * 2 + 0] = __floats2half2_rn(r0, r1);
        ((__half2*)g_ah)[(size_t)PADR * 128 + idx * 2 + 1] = __floats2half2_rn(r2, r3);
    }
}

// ---------------- head ----------------
__global__ void softmax_sum(float* __restrict__ out) {
    __shared__ float red[128][20];
    int b = blockIdx.x;
    int t = threadIdx.x;
    float acc[20];
#pragma unroll
    for (int j = 0; j < 20; ++j) acc[j] = 0.f;
    if (t < T_DIM) {
        size_t base = ((size_t)t * B_DIM + b) * 20;
        float v[20], mx = -1e30f;
#pragma unroll
        for (int j = 0; j < 20; ++j) {
            v[j] = g_logits[base + j]
                 + g_logits[(size_t)M_DIM * 20 + base + j]
                 + g_logits[(size_t)2 * M_DIM * 20 + base + j]
                 + g_logits[(size_t)3 * M_DIM * 20 + base + j];
            mx = fmaxf(mx, v[j]);
        }
        float s = 0.f;
#pragma unroll
        for (int j = 0; j < 20; ++j) { v[j] = expf(v[j] - mx); s += v[j]; }
        float inv = 1.f / s;
#pragma unroll
        for (int j = 0; j < 20; ++j) acc[j] = v[j] * inv;
    }
#pragma unroll
    for (int j = 0; j < 20; ++j) red[t][j] = acc[j];
    __syncthreads();
    for (int st = 64; st > 0; st >>= 1) {
        if (t < st)
#pragma unroll
            for (int j = 0; j < 20; ++j) red[t][j] += red[t + st][j];
        __syncthreads();
    }
    if (t < 20) out[b * 20 + t] = red[0][t];
}

// ---------------- host launch ----------------
extern "C" void kernel_launch(void* const* d_in, const int* in_sizes, int n_in,
                              void* d_out, int out_size) {
    const float* x      = (const float*)d_in[0];
    const float* W1     = (const float*)d_in[1];
    const float* P1     = (const float*)d_in[2];
    const float* W2     = (const float*)d_in[3];
    const float* P2     = (const float*)d_in[4];
    const float* W3     = (const float*)d_in[5];
    const float* P3     = (const float*)d_in[6];
    const float* gamma1 = (const float*)d_in[7];
    const float* beta1  = (const float*)d_in[8];
    const float* gamma2 = (const float*)d_in[9];
    const float* beta2  = (const float*)d_in[10];
    float* out = (float*)d_out;

    __half *p_xh, *p_ah, *p_K1h, *p_K2h, *p_K3h;
    float *p_conv, *p_logits;
    cudaGetSymbolAddress((void**)&p_xh, g_xh);
    cudaGetSymbolAddress((void**)&p_ah, g_ah);
    cudaGetSymbolAddress((void**)&p_K1h, g_K1h);
    cudaGetSymbolAddress((void**)&p_K2h, g_K2h);
    cudaGetSymbolAddress((void**)&p_K3h, g_K3h);
    cudaGetSymbolAddress((void**)&p_conv, g_conv);
    cudaGetSymbolAddress((void**)&p_logits, g_logits);

    const int SM12 = 3 * (128 * 144 + 128 * 144);   // 110592 -> 2 CTAs/SM
    const int SM3  = 3 * (128 * 144 + 32 * 144);    // 69120  -> 2 CTAs/SM
    cudaFuncSetAttribute((const void*)conv_mma<C0P, 128, 128, 4, 2, 256, 2, 3, 2, 1>,
                         cudaFuncAttributeMaxDynamicSharedMemorySize, SM12);
    cudaFuncSetAttribute((const void*)conv_mma<C1, 128, 128, 4, 2, 256, 2, 3, 2, 1>,
                         cudaFuncAttributeMaxDynamicSharedMemorySize, SM12);
    cudaFuncSetAttribute((const void*)conv_mma<C1, 128, 32, 8, 1, N3P, 1, 4, 2, 0>,
                         cudaFuncAttributeMaxDynamicSharedMemorySize, SM3);

    setup_all<<<G_INPUT + G_BUILD, 256>>>(x, W1, P1, W2, P2, W3, P3);

    // layer 1: 600 CTAs, fp16-acc HMMA with per-instruction fp32 fold
    conv_mma<C0P, 128, 128, 4, 2, 256, 2, 3, 2, 1><<<dim3(100, 6), 256, SM12>>>(
        p_xh, p_K1h, p_conv, 256, 256);
    bn_fused<<<128, 256>>>(p_conv, gamma1, beta1);

    // layer 2
    conv_mma<C1, 128, 128, 4, 2, 256, 2, 3, 2, 1><<<dim3(100, 6), 256, SM12>>>(
        p_ah, p_K2h, p_conv, 256, 256);
    bn_fused<<<128, 256>>>(p_conv, gamma2, beta2);

    // layer 3: fp32-acc (precision insurance) + head
    conv_mma<C1, 128, 32, 8, 1, N3P, 1, 4, 2, 0><<<dim3(100, 4), 256, SM3>>>(
        p_ah, p_K3h, p_logits, 20, 20);
    softmax_sum<<<B_DIM, 128>>>(out);
}

// round 16
// speedup vs baseline: 1.4008x; 1.4008x over previous
#include <cuda_runtime.h>
#include <cuda_fp16.h>
#include <math.h>
#include <stdint.h>

// ---------------- problem constants ----------------
#define T_DIM 100
#define B_DIM 128
#define C0 700
#define C0P 704
#define C1 256
#define C3 20
#define N3P 32
#define L_TAPS 25
#define PADR (24 * B_DIM)
#define M_DIM (T_DIM * B_DIM)        // 12800
#define ROWS_PAD (PADR + M_DIM)      // 15872

// ---------------- device scratch ----------------
__device__ __align__(16) __half g_xh[ROWS_PAD * C0P];
__device__ __align__(16) __half g_ah[ROWS_PAD * C1];
__device__ __align__(16) float g_conv[3 * M_DIM * C1];
__device__ __align__(16) float g_sum[M_DIM * C1];
__device__ __align__(16) float g_logits[4 * M_DIM * C3];
__device__ __align__(16) __half g_K1h[L_TAPS * C1 * C0P];
__device__ __align__(16) __half g_K2h[L_TAPS * C1 * C1];
__device__ __align__(16) __half g_K3h[L_TAPS * N3P * C1];
__device__ __align__(16) float g_part[128 * 2 * 256];
__device__ float g_scale[256];
__device__ float g_shift[256];
__device__ unsigned long long g_ticket = 0;
__device__ volatile unsigned long long g_flag = 0;

// ---------------- PTX helpers (sm_80-compatible ISA only) ----------------
__device__ __forceinline__ uint32_t smem_u32(const void* p) {
    uint32_t a;
    asm("{ .reg .u64 t; cvta.to.shared.u64 t, %1; cvt.u32.u64 %0, t; }" : "=r"(a) : "l"(p));
    return a;
}
__device__ __forceinline__ void ldsm_x4(uint32_t& r0, uint32_t& r1, uint32_t& r2, uint32_t& r3,
                                        uint32_t addr) {
    asm volatile("ldmatrix.sync.aligned.m8n8.x4.shared.b16 {%0,%1,%2,%3}, [%4];"
                 : "=r"(r0), "=r"(r1), "=r"(r2), "=r"(r3) : "r"(addr));
}
__device__ __forceinline__ void mma16816(float* c, const uint32_t* a, const uint32_t* b) {
    asm volatile(
        "mma.sync.aligned.m16n8k16.row.col.f32.f16.f16.f32 "
        "{%0,%1,%2,%3}, {%4,%5,%6,%7}, {%8,%9}, {%0,%1,%2,%3};"
        : "+f"(c[0]), "+f"(c[1]), "+f"(c[2]), "+f"(c[3])
        : "r"(a[0]), "r"(a[1]), "r"(a[2]), "r"(a[3]), "r"(b[0]), "r"(b[1]));
}
__device__ __forceinline__ void cp16(uint32_t s, const void* g) {
    asm volatile("cp.async.cg.shared.global [%0], [%1], 16;" :: "r"(s), "l"(g));
}
#define CP_COMMIT()  asm volatile("cp.async.commit_group;" ::: "memory")
#define CP_WAIT(n)   asm volatile("cp.async.wait_group %0;" :: "n"(n) : "memory")

// ---------------- fused setup kernel (float4-vectorized input path) ----------
__device__ __forceinline__ void build_elem(const float* __restrict__ W,
                                           const float* __restrict__ P,
                                           __half* __restrict__ Kh,
                                           int Cin, int Cinp, int Cout, int Npad, int idx) {
    int i = idx % Cinp;
    int n = idx / Cinp;
    if (n < Cout && i < Cin) {
        float p = P[n * Cin + i];
        float w = W[n * Cin + i];
        float k[L_TAPS], z = 0.f;
#pragma unroll
        for (int l = 0; l < L_TAPS; ++l) {
            float d = ((float)(l - 12) - p) * (1.f / 12.f);
            k[l] = expf(-0.5f * d * d);
            z += k[l];
        }
        float sc = w / (z + 1e-7f);
#pragma unroll
        for (int l = 0; l < L_TAPS; ++l)
            Kh[((size_t)l * Npad + n) * Cinp + i] = __float2half(k[l] * sc);
    } else {
#pragma unroll
        for (int l = 0; l < L_TAPS; ++l)
            Kh[((size_t)l * Npad + n) * Cinp + i] = __float2half(0.f);
    }
}

#define G_INPUT ((ROWS_PAD * C0P / 4 + 255) / 256)
#define N_BUILD (256 * C0P + 256 * C1 + N3P * C1)
#define G_BUILD ((N_BUILD + 255) / 256)

__global__ void setup_all(const float* __restrict__ x,
                          const float* __restrict__ W1, const float* __restrict__ P1,
                          const float* __restrict__ W2, const float* __restrict__ P2,
                          const float* __restrict__ W3, const float* __restrict__ P3) {
    if (blockIdx.x < G_INPUT) {
        int i = blockIdx.x * blockDim.x + threadIdx.x;
        if (i >= ROWS_PAD * C0P / 4) return;
        int c4 = (i % (C0P / 4)) * 4;
        int row = i / (C0P / 4);
        __half2 h0 = __floats2half2_rn(0.f, 0.f), h1 = h0;
        if (row >= PADR && c4 < C0) {          // 700 % 4 == 0: c4<700 => c4+3<700
            int m = row - PADR;
            int t = m >> 7, b = m & 127;
            float4 v = *(const float4*)&x[((size_t)b * T_DIM + t) * C0 + c4];
            h0 = __floats2half2_rn(v.x, v.y);
            h1 = __floats2half2_rn(v.z, v.w);
        }
        __half2* dst = (__half2*)&g_xh[(size_t)row * C0P + c4];
        dst[0] = h0; dst[1] = h1;
        if (i < PADR * C1 / 4) {
            __half2* ap = (__half2*)&g_ah[(size_t)i * 4];
            ap[0] = __floats2half2_rn(0.f, 0.f);
            ap[1] = __floats2half2_rn(0.f, 0.f);
        }
    } else {
        int i = (blockIdx.x - G_INPUT) * blockDim.x + threadIdx.x;
        const int R1 = 256 * C0P, R2 = 256 * C1, R3 = N3P * C1;
        if (i < R1) build_elem(W1, P1, g_K1h, C0, C0P, 256, 256, i);
        else if (i < R1 + R2) build_elem(W2, P2, g_K2h, C1, C1, 256, 256, i - R1);
        else if (i < R1 + R2 + R3) build_elem(W3, P3, g_K3h, C1, C1, C3, N3P, i - R1 - R2);
    }
}

// ---------------- warp-tiled mma.sync conv-GEMM (R13/R8 proven body) ----------
template <int CIN, int BM, int BN, int WR, int WC, int NTOT, int NSPLIT, int KSPLIT, int MAXOCC>
__global__ __launch_bounds__(256, MAXOCC)
void conv_mma(const __half* __restrict__ Ah, const __half* __restrict__ Bh,
              float* __restrict__ Y, int ldY, int ncol) {
    constexpr int KCH = CIN / 64;
    constexpr int NCHUNK = L_TAPS * KCH;
    constexpr int LEN = (NCHUNK + KSPLIT - 1) / KSPLIT;
    constexpr int WM = BM / WR, WN = BN / WC;
    constexpr int MT = WM / 16, NT = WN / 8;
    constexpr int ASTR = 144;
    constexpr int ASZ = BM * ASTR, BSZ = BN * ASTR;
    constexpr int STG = ASZ + BSZ;

    extern __shared__ char smem[];
    uint32_t s_base = smem_u32(smem);

    int tid = threadIdx.x, wid = tid >> 5, lane = tid & 31;
    int m0 = blockIdx.x * BM;
    int npart = blockIdx.y % NSPLIT;
    int kpart = blockIdx.y / NSPLIT;
    int n0 = npart * BN;
    int q0 = kpart * LEN;
    int q1 = (q0 + LEN < NCHUNK) ? q0 + LEN : NCHUNK;
    float* Yb = Y + (size_t)kpart * M_DIM * ldY;

    int warp_m = (wid % WR) * WM;
    int warp_n = (wid / WR) * WN;

    float acc[MT][NT][4];
#pragma unroll
    for (int i = 0; i < MT; ++i)
#pragma unroll
        for (int j = 0; j < NT; ++j)
#pragma unroll
            for (int q = 0; q < 4; ++q) acc[i][j][q] = 0.f;

    auto issue = [&](int q) {
        int s = q % 3;
        int l = q / KCH;
        int k0 = (q - l * KCH) * 64;
        const __half* Abase = Ah + (size_t)(m0 + l * B_DIM) * CIN + k0;
        const __half* Bbase = Bh + (size_t)(l * NTOT + n0) * CIN + k0;
        uint32_t as = s_base + s * STG;
        uint32_t bs = as + ASZ;
#pragma unroll
        for (int j = 0; j < BM * 8 / 256; ++j) {
            int tf = tid + j * 256;
            int r = tf >> 3, cc = (tf & 7) * 8;
            cp16(as + r * ASTR + cc * 2, Abase + (size_t)r * CIN + cc);
        }
#pragma unroll
        for (int j = 0; j < BN * 8 / 256; ++j) {
            int tf = tid + j * 256;
            int r = tf >> 3, cc = (tf & 7) * 8;
            cp16(bs + r * ASTR + cc * 2, Bbase + (size_t)r * CIN + cc);
        }
        CP_COMMIT();
    };

    issue(q0);
    if (q0 + 1 < q1) issue(q0 + 1);
    for (int q = q0; q < q1; ++q) {
        if (q == q1 - 1) { CP_WAIT(0); }
        else             { CP_WAIT(1); }
        __syncthreads();
        if (q + 2 < q1) issue(q + 2);
        int s = q % 3;
        uint32_t as = s_base + s * STG;
        uint32_t bs = as + ASZ;
#pragma unroll
        for (int kk = 0; kk < 4; ++kk) {
            uint32_t a[MT][4];
            uint32_t b[NT][2];
#pragma unroll
            for (int mt = 0; mt < MT; ++mt) {
                uint32_t addr = as + (warp_m + mt * 16 + (lane & 15)) * ASTR
                              + (kk * 16 + (lane >> 4) * 8) * 2;
                ldsm_x4(a[mt][0], a[mt][1], a[mt][2], a[mt][3], addr);
            }
#pragma unroll
            for (int nt = 0; nt < NT; nt += 2) {
                uint32_t addr = bs + (warp_n + (nt + (lane >> 4)) * 8 + (lane & 7)) * ASTR
                              + (kk * 16 + ((lane >> 3) & 1) * 8) * 2;
                ldsm_x4(b[nt][0], b[nt][1], b[nt + 1][0], b[nt + 1][1], addr);
            }
#pragma unroll
            for (int mt = 0; mt < MT; ++mt)
#pragma unroll
                for (int nt = 0; nt < NT; ++nt)
                    mma16816(acc[mt][nt], a[mt], b[nt]);
        }
    }

    int rq2 = lane >> 2, cq = (lane & 3) * 2;
#pragma unroll
    for (int mt = 0; mt < MT; ++mt)
#pragma unroll
        for (int nt = 0; nt < NT; ++nt) {
            int n = n0 + warp_n + nt * 8 + cq;
            if (n < ncol) {
                int m = m0 + warp_m + mt * 16 + rq2;
                *(float2*)&Yb[(size_t)m * ldY + n] =
                    make_float2(acc[mt][nt][0], acc[mt][nt][1]);
                *(float2*)&Yb[(size_t)(m + 8) * ldY + n] =
                    make_float2(acc[mt][nt][2], acc[mt][nt][3]);
            }
        }
}

// ---------------- fused BN (stats + finalize + ReLU->fp16), 512 threads -------
// grid MUST be 128 (<=148: all CTAs resident -> spin-wait deadlock-free).
__global__ __launch_bounds__(512, 1)
void bn_fused(const float* __restrict__ X,
              const float* __restrict__ gamma, const float* __restrict__ beta) {
    __shared__ float4 ss[8][64], qq[8][64];
    __shared__ float sh_s[2][256], sh_q[2][256];
    __shared__ unsigned long long sh_ticket;
    int bl = blockIdx.x;                 // 0..127, 100 rows each
    int cg = threadIdx.x & 63;
    int rg = threadIdx.x >> 6;           // 0..7
    int c4 = cg * 4;

    float4 s = make_float4(0.f, 0.f, 0.f, 0.f);
    float4 qv = make_float4(0.f, 0.f, 0.f, 0.f);
    for (int r = rg; r < 100; r += 8) {
        size_t idx = (size_t)(bl * 100 + r) * 64 + cg;
        float4 v0 = ((const float4*)X)[idx];
        float4 v1 = ((const float4*)X)[(size_t)M_DIM * 64 + idx];
        float4 v2 = ((const float4*)X)[(size_t)2 * M_DIM * 64 + idx];
        float4 v;
        v.x = v0.x + v1.x + v2.x; v.y = v0.y + v1.y + v2.y;
        v.z = v0.z + v1.z + v2.z; v.w = v0.w + v1.w + v2.w;
        ((float4*)g_sum)[idx] = v;
        s.x += v.x; s.y += v.y; s.z += v.z; s.w += v.w;
        qv.x += v.x * v.x; qv.y += v.y * v.y; qv.z += v.z * v.z; qv.w += v.w * v.w;
    }
    ss[rg][cg] = s; qq[rg][cg] = qv;
    __syncthreads();
    if (rg == 0) {
#pragma unroll
        for (int g = 1; g < 8; ++g) {
            float4 sg = ss[g][cg], qg = qq[g][cg];
            s.x += sg.x; s.y += sg.y; s.z += sg.z; s.w += sg.w;
            qv.x += qg.x; qv.y += qg.y; qv.z += qg.z; qv.w += qg.w;
        }
        *(float4*)&g_part[bl * 512 + c4] = s;
        *(float4*)&g_part[bl * 512 + 256 + c4] = qv;
    }
    __threadfence();
    __syncthreads();
    if (threadIdx.x == 0) sh_ticket = atomicAdd(&g_ticket, 1ULL);
    __syncthreads();
    unsigned long long ticket = sh_ticket;
    unsigned long long epoch = ticket / 128ULL;
    bool last = (ticket % 128ULL) == 127ULL;

    if (last) {
        __threadfence();                 // acquire all blocks' g_part writes
        int c = threadIdx.x & 255;
        int sub = threadIdx.x >> 8;      // 0..1, 64 slabs each
        float st = 0.f, qt = 0.f;
#pragma unroll 8
        for (int b2 = sub * 64; b2 < sub * 64 + 64; ++b2) {
            st += g_part[b2 * 512 + c];
            qt += g_part[b2 * 512 + 256 + c];
        }
        sh_s[sub][c] = st; sh_q[sub][c] = qt;
        __syncthreads();
        if (sub == 0) {
            st = sh_s[0][c] + sh_s[1][c];
            qt = sh_q[0][c] + sh_q[1][c];
            float mean = st * (1.f / (float)M_DIM);
            float var = qt * (1.f / (float)M_DIM) - mean * mean;
            float sc = gamma[c] * rsqrtf(var + 1e-5f);
            g_scale[c] = sc;
            g_shift[c] = beta[c] - mean * sc;
        }
        __threadfence();
        __syncthreads();
        if (threadIdx.x == 0) g_flag = epoch + 1ULL;
    } else {
        if (threadIdx.x == 0) {
            while (g_flag < epoch + 1ULL) { }
        }
        __syncthreads();
        __threadfence();                 // acquire scale/shift
    }

    float sc0 = g_scale[c4 + 0], sc1 = g_scale[c4 + 1];
    float sc2 = g_scale[c4 + 2], sc3 = g_scale[c4 + 3];
    float sf0 = g_shift[c4 + 0], sf1 = g_shift[c4 + 1];
    float sf2 = g_shift[c4 + 2], sf3 = g_shift[c4 + 3];
    for (int r = rg; r < 100; r += 8) {
        size_t idx = (size_t)(bl * 100 + r) * 64 + cg;
        float4 v = ((const float4*)g_sum)[idx];
        float r0 = fmaxf(sc0 * v.x + sf0, 0.f);
        float r1 = fmaxf(sc1 * v.y + sf1, 0.f);
        float r2 = fmaxf(sc2 * v.z + sf2, 0.f);
        float r3 = fmaxf(sc3 * v.w + sf3, 0.f);
        ((__half2*)g_ah)[(size_t)PADR * 128 + idx * 2 + 0] = __floats2half2_rn(r0, r1);
        ((__half2*)g_ah)[(size_t)PADR * 128 + idx * 2 + 1] = __floats2half2_rn(r2, r3);
    }
}

// ---------------- head ----------------
__global__ void softmax_sum(float* __restrict__ out) {
    __shared__ float red[128][20];
    int b = blockIdx.x;
    int t = threadIdx.x;
    float acc[20];
#pragma unroll
    for (int j = 0; j < 20; ++j) acc[j] = 0.f;
    if (t < T_DIM) {
        size_t base = ((size_t)t * B_DIM + b) * 20;
        float v[20], mx = -1e30f;
#pragma unroll
        for (int j = 0; j < 20; ++j) {
            v[j] = g_logits[base + j]
                 + g_logits[(size_t)M_DIM * 20 + base + j]
                 + g_logits[(size_t)2 * M_DIM * 20 + base + j]
                 + g_logits[(size_t)3 * M_DIM * 20 + base + j];
            mx = fmaxf(mx, v[j]);
        }
        float s = 0.f;
#pragma unroll
        for (int j = 0; j < 20; ++j) { v[j] = expf(v[j] - mx); s += v[j]; }
        float inv = 1.f / s;
#pragma unroll
        for (int j = 0; j < 20; ++j) acc[j] = v[j] * inv;
    }
#pragma unroll
    for (int j = 0; j < 20; ++j) red[t][j] = acc[j];
    __syncthreads();
    for (int st = 64; st > 0; st >>= 1) {
        if (t < st)
#pragma unroll
            for (int j = 0; j < 20; ++j) red[t][j] += red[t + st][j];
        __syncthreads();
    }
    if (t < 20) out[b * 20 + t] = red[0][t];
}

// ---------------- host launch ----------------
extern "C" void kernel_launch(void* const* d_in, const int* in_sizes, int n_in,
                              void* d_out, int out_size) {
    const float* x      = (const float*)d_in[0];
    const float* W1     = (const float*)d_in[1];
    const float* P1     = (const float*)d_in[2];
    const float* W2     = (const float*)d_in[3];
    const float* P2     = (const float*)d_in[4];
    const float* W3     = (const float*)d_in[5];
    const float* P3     = (const float*)d_in[6];
    const float* gamma1 = (const float*)d_in[7];
    const float* beta1  = (const float*)d_in[8];
    const float* gamma2 = (const float*)d_in[9];
    const float* beta2  = (const float*)d_in[10];
    float* out = (float*)d_out;

    __half *p_xh, *p_ah, *p_K1h, *p_K2h, *p_K3h;
    float *p_conv, *p_logits;
    cudaGetSymbolAddress((void**)&p_xh, g_xh);
    cudaGetSymbolAddress((void**)&p_ah, g_ah);
    cudaGetSymbolAddress((void**)&p_K1h, g_K1h);
    cudaGetSymbolAddress((void**)&p_K2h, g_K2h);
    cudaGetSymbolAddress((void**)&p_K3h, g_K3h);
    cudaGetSymbolAddress((void**)&p_conv, g_conv);
    cudaGetSymbolAddress((void**)&p_logits, g_logits);

    const int SM12 = 3 * (128 * 144 + 128 * 144);   // 110592 -> 2 CTAs/SM
    const int SM3  = 3 * (128 * 144 + 32 * 144);    // 69120  -> 2 CTAs/SM
    cudaFuncSetAttribute((const void*)conv_mma<C0P, 128, 128, 4, 2, 256, 2, 3, 2>,
                         cudaFuncAttributeMaxDynamicSharedMemorySize, SM12);
    cudaFuncSetAttribute((const void*)conv_mma<C1, 128, 128, 4, 2, 256, 2, 3, 2>,
                         cudaFuncAttributeMaxDynamicSharedMemorySize, SM12);
    cudaFuncSetAttribute((const void*)conv_mma<C1, 128, 32, 8, 1, N3P, 1, 4, 2>,
                         cudaFuncAttributeMaxDynamicSharedMemorySize, SM3);

    setup_all<<<G_INPUT + G_BUILD, 256>>>(x, W1, P1, W2, P2, W3, P3);

    // layer 1: 600 CTAs
    conv_mma<C0P, 128, 128, 4, 2, 256, 2, 3, 2><<<dim3(100, 6), 256, SM12>>>(
        p_xh, p_K1h, p_conv, 256, 256);
    bn_fused<<<128, 512>>>(p_conv, gamma1, beta1);

    // layer 2
    conv_mma<C1, 128, 128, 4, 2, 256, 2, 3, 2><<<dim3(100, 6), 256, SM12>>>(
        p_ah, p_K2h, p_conv, 256, 256);
    bn_fused<<<128, 512>>>(p_conv, gamma2, beta2);

    // layer 3: 400 CTAs, occ 2 + head
    conv_mma<C1, 128, 32, 8, 1, N3P, 1, 4, 2><<<dim3(100, 4), 256, SM3>>>(
        p_ah, p_K3h, p_logits, 20, 20);
    softmax_sum<<<B_DIM, 128>>>(out);
}

// round 17
// speedup vs baseline: 1.4287x; 1.0199x over previous
#include <cuda_runtime.h>
#include <cuda_fp16.h>
#include <math.h>
#include <stdint.h>

// ---------------- problem constants ----------------
#define T_DIM 100
#define B_DIM 128
#define C0 700
#define C0P 704
#define C1 256
#define C3 20
#define N3P 32
#define L_TAPS 25
#define PADR (24 * B_DIM)
#define M_DIM (T_DIM * B_DIM)        // 12800
#define ROWS_PAD (PADR + M_DIM)      // 15872

// ---------------- device scratch ----------------
__device__ __align__(16) __half g_xh[ROWS_PAD * C0P];
__device__ __align__(16) __half g_ah[ROWS_PAD * C1];
__device__ __align__(16) float g_conv[3 * M_DIM * C1];
__device__ __align__(16) float g_logits[4 * M_DIM * C3];
__device__ __align__(16) __half g_K1h[L_TAPS * C1 * C0P];
__device__ __align__(16) __half g_K2h[L_TAPS * C1 * C1];
__device__ __align__(16) __half g_K3h[L_TAPS * N3P * C1];
__device__ __align__(16) float g_part[100 * 2 * 256];
__device__ float g_scale[256];
__device__ float g_shift[256];
__device__ unsigned long long g_ticket = 0;
__device__ volatile unsigned long long g_flag = 0;

// ---------------- PTX helpers (sm_80-compatible ISA only) ----------------
__device__ __forceinline__ uint32_t smem_u32(const void* p) {
    uint32_t a;
    asm("{ .reg .u64 t; cvta.to.shared.u64 t, %1; cvt.u32.u64 %0, t; }" : "=r"(a) : "l"(p));
    return a;
}
__device__ __forceinline__ void ldsm_x4(uint32_t& r0, uint32_t& r1, uint32_t& r2, uint32_t& r3,
                                        uint32_t addr) {
    asm volatile("ldmatrix.sync.aligned.m8n8.x4.shared.b16 {%0,%1,%2,%3}, [%4];"
                 : "=r"(r0), "=r"(r1), "=r"(r2), "=r"(r3) : "r"(addr));
}
__device__ __forceinline__ void mma16816(float* c, const uint32_t* a, const uint32_t* b) {
    asm volatile(
        "mma.sync.aligned.m16n8k16.row.col.f32.f16.f16.f32 "
        "{%0,%1,%2,%3}, {%4,%5,%6,%7}, {%8,%9}, {%0,%1,%2,%3};"
        : "+f"(c[0]), "+f"(c[1]), "+f"(c[2]), "+f"(c[3])
        : "r"(a[0]), "r"(a[1]), "r"(a[2]), "r"(a[3]), "r"(b[0]), "r"(b[1]));
}
__device__ __forceinline__ void cp16(uint32_t s, const void* g) {
    asm volatile("cp.async.cg.shared.global [%0], [%1], 16;" :: "r"(s), "l"(g));
}
#define CP_COMMIT()  asm volatile("cp.async.commit_group;" ::: "memory")
#define CP_WAIT(n)   asm volatile("cp.async.wait_group %0;" :: "n"(n) : "memory")

// ---------------- fused setup kernel (float4-vectorized input path) ----------
__device__ __forceinline__ void build_elem(const float* __restrict__ W,
                                           const float* __restrict__ P,
                                           __half* __restrict__ Kh,
                                           int Cin, int Cinp, int Cout, int Npad, int idx) {
    int i = idx % Cinp;
    int n = idx / Cinp;
    if (n < Cout && i < Cin) {
        float p = P[n * Cin + i];
        float w = W[n * Cin + i];
        float k[L_TAPS], z = 0.f;
#pragma unroll
        for (int l = 0; l < L_TAPS; ++l) {
            float d = ((float)(l - 12) - p) * (1.f / 12.f);
            k[l] = expf(-0.5f * d * d);
            z += k[l];
        }
        float sc = w / (z + 1e-7f);
#pragma unroll
        for (int l = 0; l < L_TAPS; ++l)
            Kh[((size_t)l * Npad + n) * Cinp + i] = __float2half(k[l] * sc);
    } else {
#pragma unroll
        for (int l = 0; l < L_TAPS; ++l)
            Kh[((size_t)l * Npad + n) * Cinp + i] = __float2half(0.f);
    }
}

#define G_INPUT ((ROWS_PAD * C0P / 4 + 255) / 256)
#define N_BUILD (256 * C0P + 256 * C1 + N3P * C1)
#define G_BUILD ((N_BUILD + 255) / 256)

__global__ void setup_all(const float* __restrict__ x,
                          const float* __restrict__ W1, const float* __restrict__ P1,
                          const float* __restrict__ W2, const float* __restrict__ P2,
                          const float* __restrict__ W3, const float* __restrict__ P3) {
    if (blockIdx.x < G_INPUT) {
        int i = blockIdx.x * blockDim.x + threadIdx.x;
        if (i >= ROWS_PAD * C0P / 4) return;
        int c4 = (i % (C0P / 4)) * 4;
        int row = i / (C0P / 4);
        __half2 h0 = __floats2half2_rn(0.f, 0.f), h1 = h0;
        if (row >= PADR && c4 < C0) {          // 700 % 4 == 0: c4<700 => c4+3<700
            int m = row - PADR;
            int t = m >> 7, b = m & 127;
            float4 v = *(const float4*)&x[((size_t)b * T_DIM + t) * C0 + c4];
            h0 = __floats2half2_rn(v.x, v.y);
            h1 = __floats2half2_rn(v.z, v.w);
        }
        __half2* dst = (__half2*)&g_xh[(size_t)row * C0P + c4];
        dst[0] = h0; dst[1] = h1;
        if (i < PADR * C1 / 4) {
            __half2* ap = (__half2*)&g_ah[(size_t)i * 4];
            ap[0] = __floats2half2_rn(0.f, 0.f);
            ap[1] = __floats2half2_rn(0.f, 0.f);
        }
    } else {
        int i = (blockIdx.x - G_INPUT) * blockDim.x + threadIdx.x;
        const int R1 = 256 * C0P, R2 = 256 * C1, R3 = N3P * C1;
        if (i < R1) build_elem(W1, P1, g_K1h, C0, C0P, 256, 256, i);
        else if (i < R1 + R2) build_elem(W2, P2, g_K2h, C1, C1, 256, 256, i - R1);
        else if (i < R1 + R2 + R3) build_elem(W3, P3, g_K3h, C1, C1, C3, N3P, i - R1 - R2);
    }
}

// ---------------- warp-tiled mma.sync conv-GEMM (R13/R8 proven body) ----------
template <int CIN, int BM, int BN, int WR, int WC, int NTOT, int NSPLIT, int KSPLIT, int MAXOCC>
__global__ __launch_bounds__(256, MAXOCC)
void conv_mma(const __half* __restrict__ Ah, const __half* __restrict__ Bh,
              float* __restrict__ Y, int ldY, int ncol) {
    constexpr int KCH = CIN / 64;
    constexpr int NCHUNK = L_TAPS * KCH;
    constexpr int LEN = (NCHUNK + KSPLIT - 1) / KSPLIT;
    constexpr int WM = BM / WR, WN = BN / WC;
    constexpr int MT = WM / 16, NT = WN / 8;
    constexpr int ASTR = 144;
    constexpr int ASZ = BM * ASTR, BSZ = BN * ASTR;
    constexpr int STG = ASZ + BSZ;

    extern __shared__ char smem[];
    uint32_t s_base = smem_u32(smem);

    int tid = threadIdx.x, wid = tid >> 5, lane = tid & 31;
    int m0 = blockIdx.x * BM;
    int npart = blockIdx.y % NSPLIT;
    int kpart = blockIdx.y / NSPLIT;
    int n0 = npart * BN;
    int q0 = kpart * LEN;
    int q1 = (q0 + LEN < NCHUNK) ? q0 + LEN : NCHUNK;
    float* Yb = Y + (size_t)kpart * M_DIM * ldY;

    int warp_m = (wid % WR) * WM;
    int warp_n = (wid / WR) * WN;

    float acc[MT][NT][4];
#pragma unroll
    for (int i = 0; i < MT; ++i)
#pragma unroll
        for (int j = 0; j < NT; ++j)
#pragma unroll
            for (int q = 0; q < 4; ++q) acc[i][j][q] = 0.f;

    auto issue = [&](int q) {
        int s = q % 3;
        int l = q / KCH;
        int k0 = (q - l * KCH) * 64;
        const __half* Abase = Ah + (size_t)(m0 + l * B_DIM) * CIN + k0;
        const __half* Bbase = Bh + (size_t)(l * NTOT + n0) * CIN + k0;
        uint32_t as = s_base + s * STG;
        uint32_t bs = as + ASZ;
#pragma unroll
        for (int j = 0; j < BM * 8 / 256; ++j) {
            int tf = tid + j * 256;
            int r = tf >> 3, cc = (tf & 7) * 8;
            cp16(as + r * ASTR + cc * 2, Abase + (size_t)r * CIN + cc);
        }
#pragma unroll
        for (int j = 0; j < BN * 8 / 256; ++j) {
            int tf = tid + j * 256;
            int r = tf >> 3, cc = (tf & 7) * 8;
            cp16(bs + r * ASTR + cc * 2, Bbase + (size_t)r * CIN + cc);
        }
        CP_COMMIT();
    };

    issue(q0);
    if (q0 + 1 < q1) issue(q0 + 1);
    for (int q = q0; q < q1; ++q) {
        if (q == q1 - 1) { CP_WAIT(0); }
        else             { CP_WAIT(1); }
        __syncthreads();
        if (q + 2 < q1) issue(q + 2);
        int s = q % 3;
        uint32_t as = s_base + s * STG;
        uint32_t bs = as + ASZ;
#pragma unroll
        for (int kk = 0; kk < 4; ++kk) {
            uint32_t a[MT][4];
            uint32_t b[NT][2];
#pragma unroll
            for (int mt = 0; mt < MT; ++mt) {
                uint32_t addr = as + (warp_m + mt * 16 + (lane & 15)) * ASTR
                              + (kk * 16 + (lane >> 4) * 8) * 2;
                ldsm_x4(a[mt][0], a[mt][1], a[mt][2], a[mt][3], addr);
            }
#pragma unroll
            for (int nt = 0; nt < NT; nt += 2) {
                uint32_t addr = bs + (warp_n + (nt + (lane >> 4)) * 8 + (lane & 7)) * ASTR
                              + (kk * 16 + ((lane >> 3) & 1) * 8) * 2;
                ldsm_x4(b[nt][0], b[nt][1], b[nt + 1][0], b[nt + 1][1], addr);
            }
#pragma unroll
            for (int mt = 0; mt < MT; ++mt)
#pragma unroll
                for (int nt = 0; nt < NT; ++nt)
                    mma16816(acc[mt][nt], a[mt], b[nt]);
        }
    }

    int rq2 = lane >> 2, cq = (lane & 3) * 2;
#pragma unroll
    for (int mt = 0; mt < MT; ++mt)
#pragma unroll
        for (int nt = 0; nt < NT; ++nt) {
            int n = n0 + warp_n + nt * 8 + cq;
            if (n < ncol) {
                int m = m0 + warp_m + mt * 16 + rq2;
                *(float2*)&Yb[(size_t)m * ldY + n] =
                    make_float2(acc[mt][nt][0], acc[mt][nt][1]);
                *(float2*)&Yb[(size_t)(m + 8) * ldY + n] =
                    make_float2(acc[mt][nt][2], acc[mt][nt][3]);
            }
        }
}

// ---------------- fused BN, register-resident values across the barrier -------
// grid MUST be 100 (<=148: all CTAs resident -> spin-wait deadlock-free).
// Each block: 128 rows; each thread: 16 rows x 4 channels held in registers.
__global__ __launch_bounds__(512, 1)
void bn_fused(const float* __restrict__ X,
              const float* __restrict__ gamma, const float* __restrict__ beta) {
    __shared__ float4 ss[8][64], qq[8][64];
    __shared__ float sh_s[2][256], sh_q[2][256];
    __shared__ unsigned long long sh_ticket;
    int bl = blockIdx.x;                 // 0..99, 128 rows each
    int cg = threadIdx.x & 63;
    int rg = threadIdx.x >> 6;           // 0..7
    int c4 = cg * 4;

    float4 vals[16];
    float4 s = make_float4(0.f, 0.f, 0.f, 0.f);
    float4 qv = make_float4(0.f, 0.f, 0.f, 0.f);
#pragma unroll
    for (int k = 0; k < 16; ++k) {
        int r = rg + k * 8;
        size_t idx = (size_t)(bl * 128 + r) * 64 + cg;
        float4 v0 = ((const float4*)X)[idx];
        float4 v1 = ((const float4*)X)[(size_t)M_DIM * 64 + idx];
        float4 v2 = ((const float4*)X)[(size_t)2 * M_DIM * 64 + idx];
        float4 v;
        v.x = v0.x + v1.x + v2.x; v.y = v0.y + v1.y + v2.y;
        v.z = v0.z + v1.z + v2.z; v.w = v0.w + v1.w + v2.w;
        vals[k] = v;
        s.x += v.x; s.y += v.y; s.z += v.z; s.w += v.w;
        qv.x += v.x * v.x; qv.y += v.y * v.y; qv.z += v.z * v.z; qv.w += v.w * v.w;
    }
    ss[rg][cg] = s; qq[rg][cg] = qv;
    __syncthreads();
    if (rg == 0) {
#pragma unroll
        for (int g = 1; g < 8; ++g) {
            float4 sg = ss[g][cg], qg = qq[g][cg];
            s.x += sg.x; s.y += sg.y; s.z += sg.z; s.w += sg.w;
            qv.x += qg.x; qv.y += qg.y; qv.z += qg.z; qv.w += qg.w;
        }
        *(float4*)&g_part[bl * 512 + c4] = s;
        *(float4*)&g_part[bl * 512 + 256 + c4] = qv;
    }
    __threadfence();
    __syncthreads();
    if (threadIdx.x == 0) sh_ticket = atomicAdd(&g_ticket, 1ULL);
    __syncthreads();
    unsigned long long ticket = sh_ticket;
    unsigned long long epoch = ticket / 100ULL;
    bool last = (ticket % 100ULL) == 99ULL;

    if (last) {
        __threadfence();                 // acquire all blocks' g_part writes
        int c = threadIdx.x & 255;
        int sub = threadIdx.x >> 8;      // 0..1, 50 slabs each
        float st = 0.f, qt = 0.f;
#pragma unroll 5
        for (int b2 = sub * 50; b2 < sub * 50 + 50; ++b2) {
            st += g_part[b2 * 512 + c];
            qt += g_part[b2 * 512 + 256 + c];
        }
        sh_s[sub][c] = st; sh_q[sub][c] = qt;
        __syncthreads();
        if (sub == 0) {
            st = sh_s[0][c] + sh_s[1][c];
            qt = sh_q[0][c] + sh_q[1][c];
            float mean = st * (1.f / (float)M_DIM);
            float var = qt * (1.f / (float)M_DIM) - mean * mean;
            float sc = gamma[c] * rsqrtf(var + 1e-5f);
            g_scale[c] = sc;
            g_shift[c] = beta[c] - mean * sc;
        }
        __threadfence();
        __syncthreads();
        if (threadIdx.x == 0) g_flag = epoch + 1ULL;
    } else {
        if (threadIdx.x == 0) {
            while (g_flag < epoch + 1ULL) { }
        }
        __syncthreads();
        __threadfence();                 // acquire scale/shift
    }

    float sc0 = g_scale[c4 + 0], sc1 = g_scale[c4 + 1];
    float sc2 = g_scale[c4 + 2], sc3 = g_scale[c4 + 3];
    float sf0 = g_shift[c4 + 0], sf1 = g_shift[c4 + 1];
    float sf2 = g_shift[c4 + 2], sf3 = g_shift[c4 + 3];
#pragma unroll
    for (int k = 0; k < 16; ++k) {
        int r = rg + k * 8;
        size_t idx = (size_t)(bl * 128 + r) * 64 + cg;
        float4 v = vals[k];
        float r0 = fmaxf(sc0 * v.x + sf0, 0.f);
        float r1 = fmaxf(sc1 * v.y + sf1, 0.f);
        float r2 = fmaxf(sc2 * v.z + sf2, 0.f);
        float r3 = fmaxf(sc3 * v.w + sf3, 0.f);
        ((__half2*)g_ah)[(size_t)PADR * 128 + idx * 2 + 0] = __floats2half2_rn(r0, r1);
        ((__half2*)g_ah)[(size_t)PADR * 128 + idx * 2 + 1] = __floats2half2_rn(r2, r3);
    }
}

// ---------------- head ----------------
__global__ void softmax_sum(float* __restrict__ out) {
    __shared__ float red[128][20];
    int b = blockIdx.x;
    int t = threadIdx.x;
    float acc[20];
#pragma unroll
    for (int j = 0; j < 20; ++j) acc[j] = 0.f;
    if (t < T_DIM) {
        size_t base = ((size_t)t * B_DIM + b) * 20;
        float v[20], mx = -1e30f;
#pragma unroll
        for (int j = 0; j < 20; ++j) {
            v[j] = g_logits[base + j]
                 + g_logits[(size_t)M_DIM * 20 + base + j]
                 + g_logits[(size_t)2 * M_DIM * 20 + base + j]
                 + g_logits[(size_t)3 * M_DIM * 20 + base + j];
            mx = fmaxf(mx, v[j]);
        }
        float s = 0.f;
#pragma unroll
        for (int j = 0; j < 20; ++j) { v[j] = expf(v[j] - mx); s += v[j]; }
        float inv = 1.f / s;
#pragma unroll
        for (int j = 0; j < 20; ++j) acc[j] = v[j] * inv;
    }
#pragma unroll
    for (int j = 0; j < 20; ++j) red[t][j] = acc[j];
    __syncthreads();
    for (int st = 64; st > 0; st >>= 1) {
        if (t < st)
#pragma unroll
            for (int j = 0; j < 20; ++j) red[t][j] += red[t + st][j];
        __syncthreads();
    }
    if (t < 20) out[b * 20 + t] = red[0][t];
}

// ---------------- host launch ----------------
extern "C" void kernel_launch(void* const* d_in, const int* in_sizes, int n_in,
                              void* d_out, int out_size) {
    const float* x      = (const float*)d_in[0];
    const float* W1     = (const float*)d_in[1];
    const float* P1     = (const float*)d_in[2];
    const float* W2     = (const float*)d_in[3];
    const float* P2     = (const float*)d_in[4];
    const float* W3     = (const float*)d_in[5];
    const float* P3     = (const float*)d_in[6];
    const float* gamma1 = (const float*)d_in[7];
    const float* beta1  = (const float*)d_in[8];
    const float* gamma2 = (const float*)d_in[9];
    const float* beta2  = (const float*)d_in[10];
    float* out = (float*)d_out;

    __half *p_xh, *p_ah, *p_K1h, *p_K2h, *p_K3h;
    float *p_conv, *p_logits;
    cudaGetSymbolAddress((void**)&p_xh, g_xh);
    cudaGetSymbolAddress((void**)&p_ah, g_ah);
    cudaGetSymbolAddress((void**)&p_K1h, g_K1h);
    cudaGetSymbolAddress((void**)&p_K2h, g_K2h);
    cudaGetSymbolAddress((void**)&p_K3h, g_K3h);
    cudaGetSymbolAddress((void**)&p_conv, g_conv);
    cudaGetSymbolAddress((void**)&p_logits, g_logits);

    const int SM12 = 3 * (128 * 144 + 128 * 144);   // 110592 -> 2 CTAs/SM
    const int SM3  = 3 * (128 * 144 + 32 * 144);    // 69120  -> 2 CTAs/SM
    cudaFuncSetAttribute((const void*)conv_mma<C0P, 128, 128, 4, 2, 256, 2, 3, 2>,
                         cudaFuncAttributeMaxDynamicSharedMemorySize, SM12);
    cudaFuncSetAttribute((const void*)conv_mma<C1, 128, 128, 4, 2, 256, 2, 3, 2>,
                         cudaFuncAttributeMaxDynamicSharedMemorySize, SM12);
    cudaFuncSetAttribute((const void*)conv_mma<C1, 128, 32, 8, 1, N3P, 1, 4, 2>,
                         cudaFuncAttributeMaxDynamicSharedMemorySize, SM3);

    setup_all<<<G_INPUT + G_BUILD, 256>>>(x, W1, P1, W2, P2, W3, P3);

    // layer 1: 600 CTAs
    conv_mma<C0P, 128, 128, 4, 2, 256, 2, 3, 2><<<dim3(100, 6), 256, SM12>>>(
        p_xh, p_K1h, p_conv, 256, 256);
    bn_fused<<<100, 512>>>(p_conv, gamma1, beta1);

    // layer 2
    conv_mma<C1, 128, 128, 4, 2, 256, 2, 3, 2><<<dim3(100, 6), 256, SM12>>>(
        p_ah, p_K2h, p_conv, 256, 256);
    bn_fused<<<100, 512>>>(p_conv, gamma2, beta2);

    // layer 3: 400 CTAs, occ 2 + head
    conv_mma<C1, 128, 32, 8, 1, N3P, 1, 4, 2><<<dim3(100, 4), 256, SM3>>>(
        p_ah, p_K3h, p_logits, 20, 20);
    softmax_sum<<<B_DIM, 128>>>(out);
}